// round 1
// baseline (speedup 1.0000x reference)
#include <cuda_runtime.h>
#include <cstdint>

#define HID    1024
#define INPD   512
#define BATCH  128
#define TSTEPS 256
#define G4H    4096
#define KC     32

// ---- device-global scratch (no allocations allowed) ----
__device__ float    g_XS[134217728];        // [t][gate*1024+j][b]  fp32, 512 MB
__device__ float    g_H[2][HID * BATCH];    // h ping-pong
__device__ unsigned g_bar;                  // software grid barrier counter

__device__ __forceinline__ uint32_t f2tf(float f) {
    uint32_t u;
    asm("cvt.rna.tf32.f32 %0, %1;" : "=r"(u) : "f"(f));
    return u;
}

__device__ __forceinline__ void mma8(float* d, const uint32_t* a, const uint32_t* b) {
    asm volatile(
        "mma.sync.aligned.m16n8k8.row.col.f32.tf32.tf32.f32 "
        "{%0,%1,%2,%3}, {%4,%5,%6,%7}, {%8,%9}, {%0,%1,%2,%3};"
        : "+f"(d[0]), "+f"(d[1]), "+f"(d[2]), "+f"(d[3])
        : "r"(a[0]), "r"(a[1]), "r"(a[2]), "r"(a[3]), "r"(b[0]), "r"(b[1]));
}

__device__ __forceinline__ const float* sel4(const float* a, const float* b,
                                             const float* c, const float* d, int g) {
    return g == 0 ? a : (g == 1 ? b : (g == 2 ? c : d));
}

__device__ __forceinline__ float sigm(float x) { return 1.0f / (1.0f + expf(-x)); }

// ============================================================================
// Kernel 1: XS[t][gate*1024+j][b] = sum_i Wx[gate][j][i] * x[b][t][i] + bias
// grid (64, 256): blockIdx.x = hidden-chunk (16 units), blockIdx.y = t
// block tile: M=64 rows (4 gates x 16 units) x N=128 batch, K=512
// ============================================================================
__global__ void __launch_bounds__(256) xproj_kernel(
    const float* __restrict__ x,
    const float* __restrict__ Wg, const float* __restrict__ Wi,
    const float* __restrict__ Wf, const float* __restrict__ Wo,
    const float* __restrict__ bg, const float* __restrict__ bi,
    const float* __restrict__ bf, const float* __restrict__ bo)
{
    __shared__ uint32_t sA[64][36];   // padded: conflict-free frag loads
    __shared__ uint32_t sB[KC][136];

    const int tid = threadIdx.x;
    const int t   = blockIdx.y;
    const int j0  = blockIdx.x * 16;
    if (blockIdx.x == 0 && blockIdx.y == 0 && tid == 0) g_bar = 0;  // reset barrier for lstm kernel

    const int warp = tid >> 5, lane = tid & 31;
    const int wm = warp & 3, wn = warp >> 2;       // 4 M-warps (one per gate) x 2 N-warps
    const int gid = lane >> 2, tig = lane & 3;

    float acc[8][4];
#pragma unroll
    for (int i = 0; i < 8; ++i) { acc[i][0] = acc[i][1] = acc[i][2] = acc[i][3] = 0.f; }

#pragma unroll 1
    for (int kc = 0; kc < INPD / KC; ++kc) {
#pragma unroll
        for (int i = 0; i < 8; ++i) {               // A: 64 rows x 32 k
            int idx = i * 256 + tid, r = idx >> 5, k = idx & 31;
            const float* W = sel4(Wg, Wi, Wf, Wo, r >> 4);
            sA[r][k] = f2tf(W[(size_t)(j0 + (r & 15)) * INPD + kc * KC + k]);
        }
#pragma unroll
        for (int i = 0; i < 16; ++i) {              // B: 32 k x 128 b from x[b][t][k]
            int idx = i * 256 + tid, b = idx >> 5, k = idx & 31;
            sB[k][b] = f2tf(x[(size_t)b * (TSTEPS * INPD) + (size_t)t * INPD + kc * KC + k]);
        }
        __syncthreads();
#pragma unroll
        for (int ks = 0; ks < 4; ++ks) {
            const int k8 = ks * 8;
            uint32_t a[4];
            a[0] = sA[wm * 16 + gid][k8 + tig];
            a[1] = sA[wm * 16 + gid + 8][k8 + tig];
            a[2] = sA[wm * 16 + gid][k8 + tig + 4];
            a[3] = sA[wm * 16 + gid + 8][k8 + tig + 4];
#pragma unroll
            for (int nf = 0; nf < 8; ++nf) {
                const int n = wn * 64 + nf * 8 + gid;
                uint32_t bb[2] = { sB[k8 + tig][n], sB[k8 + tig + 4][n] };
                mma8(acc[nf], a, bb);
            }
        }
        __syncthreads();
    }

    const float* bptr = sel4(bg, bi, bf, bo, wm);
    const float b0v = bptr[j0 + gid];
    const float b1v = bptr[j0 + gid + 8];
    const size_t base = (size_t)t * G4H * BATCH;
    const int g0 = wm * 1024 + j0 + gid;
#pragma unroll
    for (int nf = 0; nf < 8; ++nf) {
        const int n = wn * 64 + nf * 8 + tig * 2;
        float* p0 = &g_XS[base + (size_t)g0 * BATCH + n];
        float* p1 = &g_XS[base + (size_t)(g0 + 8) * BATCH + n];
        p0[0] = acc[nf][0] + b0v; p0[1] = acc[nf][1] + b0v;
        p1[0] = acc[nf][2] + b1v; p1[1] = acc[nf][3] + b1v;
    }
}

// ============================================================================
// Kernel 2: persistent recurrent kernel. 64 blocks, each owns 16 hidden units
// (all 4 gates, full batch). c state in registers for all 256 steps.
// Software grid barrier between steps (all 64 blocks co-resident on 148 SMs).
// ============================================================================
struct SmemU {
    union {
        struct { uint32_t A[64][36]; uint32_t B[KC][136]; } ab;
        float zs[64][136];
    };
};

__global__ void __launch_bounds__(256) lstm_kernel(
    const float* __restrict__ h0, const float* __restrict__ c0,
    const float* __restrict__ Wg, const float* __restrict__ Wi,
    const float* __restrict__ Wf, const float* __restrict__ Wo,
    float* __restrict__ out)
{
    __shared__ SmemU sm;
    const int tid = threadIdx.x;
    const int j0  = blockIdx.x * 16;
    const int warp = tid >> 5, lane = tid & 31;
    const int wm = warp & 3, wn = warp >> 2;
    const int gid = lane >> 2, tig = lane & 3;

    // per-thread slice of c state: 8 (j,b) pairs, held in registers across all steps
    float creg[8];
#pragma unroll
    for (int e = 0; e < 8; ++e) {
        int idx = e * 256 + tid, jj = idx >> 7, b = idx & 127;
        creg[e] = c0[(j0 + jj) * BATCH + b];
    }

#pragma unroll 1
    for (int t = 0; t < TSTEPS; ++t) {
        const float* hin = (t == 0) ? h0 : g_H[(t + 1) & 1];

        float acc[8][4];
#pragma unroll
        for (int i = 0; i < 8; ++i) { acc[i][0] = acc[i][1] = acc[i][2] = acc[i][3] = 0.f; }

#pragma unroll 1
        for (int kc = 0; kc < HID / KC; ++kc) {
#pragma unroll
            for (int i = 0; i < 8; ++i) {           // A: Wh rows (64 x 32)
                int idx = i * 256 + tid, r = idx >> 5, k = idx & 31;
                const float* W = sel4(Wg, Wi, Wf, Wo, r >> 4);
                sm.ab.A[r][k] = f2tf(W[(size_t)(j0 + (r & 15)) * HID + kc * KC + k]);
            }
#pragma unroll
            for (int i = 0; i < 16; ++i) {          // B: h[k][b] (32 x 128)
                int idx = i * 256 + tid, k = idx >> 7, b = idx & 127;
                sm.ab.B[k][b] = f2tf(hin[(kc * KC + k) * BATCH + b]);
            }
            __syncthreads();
#pragma unroll
            for (int ks = 0; ks < 4; ++ks) {
                const int k8 = ks * 8;
                uint32_t a[4];
                a[0] = sm.ab.A[wm * 16 + gid][k8 + tig];
                a[1] = sm.ab.A[wm * 16 + gid + 8][k8 + tig];
                a[2] = sm.ab.A[wm * 16 + gid][k8 + tig + 4];
                a[3] = sm.ab.A[wm * 16 + gid + 8][k8 + tig + 4];
#pragma unroll
                for (int nf = 0; nf < 8; ++nf) {
                    const int n = wn * 64 + nf * 8 + gid;
                    uint32_t bb[2] = { sm.ab.B[k8 + tig][n], sm.ab.B[k8 + tig + 4][n] };
                    mma8(acc[nf], a, bb);
                }
            }
            __syncthreads();
        }

        // stage z tile into smem so each thread can gather all 4 gates of its (j,b)
#pragma unroll
        for (int nf = 0; nf < 8; ++nf) {
            const int n = wn * 64 + nf * 8 + tig * 2;
            sm.zs[wm * 16 + gid][n]         = acc[nf][0];
            sm.zs[wm * 16 + gid][n + 1]     = acc[nf][1];
            sm.zs[wm * 16 + gid + 8][n]     = acc[nf][2];
            sm.zs[wm * 16 + gid + 8][n + 1] = acc[nf][3];
        }
        __syncthreads();

        float* hw = g_H[t & 1];
        const size_t xb = (size_t)t * G4H * BATCH;
#pragma unroll
        for (int e = 0; e < 8; ++e) {
            int idx = e * 256 + tid, jj = idx >> 7, b = idx & 127;
            const size_t row = (size_t)(j0 + jj) * BATCH + b;
            float zg = sm.zs[jj][b]      + g_XS[xb + row];
            float zi = sm.zs[16 + jj][b] + g_XS[xb + (size_t)1024 * BATCH + row];
            float zf = sm.zs[32 + jj][b] + g_XS[xb + (size_t)2048 * BATCH + row];
            float zo = sm.zs[48 + jj][b] + g_XS[xb + (size_t)3072 * BATCH + row];
            float cv = tanhf(zg) * sigm(zi) + creg[e] * sigm(zf);
            creg[e] = cv;
            float hv = tanhf(cv) * sigm(zo);
            hw[row] = hv;
            if (t == TSTEPS - 1) out[row] = hv;
        }
        __syncthreads();

        // grid barrier: release h writes, arrive, spin until all 64 blocks arrived
        if (tid == 0) {
            __threadfence();
            atomicAdd(&g_bar, 1u);
            const unsigned target = (unsigned)(t + 1) * gridDim.x;
            const volatile unsigned* p = &g_bar;
            while (*p < target) { __nanosleep(64); }
            __threadfence();
        }
        __syncthreads();
    }
}

// ============================================================================
extern "C" void kernel_launch(void* const* d_in, const int* in_sizes, int n_in,
                              void* d_out, int out_size)
{
    const float* x   = (const float*)d_in[0];
    const float* c0  = (const float*)d_in[1];
    const float* h0  = (const float*)d_in[2];
    const float* Wgx = (const float*)d_in[3];
    const float* Wix = (const float*)d_in[4];
    const float* Wfx = (const float*)d_in[5];
    const float* Wox = (const float*)d_in[6];
    const float* Wgh = (const float*)d_in[7];
    const float* Wih = (const float*)d_in[8];
    const float* Wfh = (const float*)d_in[9];
    const float* Woh = (const float*)d_in[10];
    const float* bg  = (const float*)d_in[11];
    const float* bi  = (const float*)d_in[12];
    const float* bf  = (const float*)d_in[13];
    const float* bo  = (const float*)d_in[14];
    float* out = (float*)d_out;

    dim3 gproj(64, TSTEPS, 1);
    xproj_kernel<<<gproj, 256>>>(x, Wgx, Wix, Wfx, Wox, bg, bi, bf, bo);
    lstm_kernel<<<64, 256>>>(h0, c0, Wgh, Wih, Wfh, Woh, out);
}